// round 6
// baseline (speedup 1.0000x reference)
#include <cuda_runtime.h>
#include <cstdint>

#define OBS_DIM 256
#define POP_DIM 10
#define NIN     (OBS_DIM * POP_DIM)   // 2560
#define HID1    256
#define HID2    256
#define OUTP    80                    // ACT_DIM * DE_POP
#define ACT_DIM 8
#define DE_POP  10
#define T       25
#define ENC_VTH 0.999f

// ---------------- scratch: transposed weights (column-contiguous gathers) ----------------
__device__ float g_W1T[NIN  * HID1];   // [j][h]  (2.62 MB, L2-resident)
__device__ float g_W2T[HID1 * HID2];   // [j][h]
__device__ float g_W3T[HID2 * OUTP];   // [j][o]

__global__ void k_t1(const float* __restrict__ w1) {  // w1[HID1][NIN] -> g_W1T[NIN][HID1]
    int idx = blockIdx.x * blockDim.x + threadIdx.x;
    if (idx < HID1 * NIN) { int h = idx / NIN, j = idx - h * NIN; g_W1T[j * HID1 + h] = w1[idx]; }
}
__global__ void k_t2(const float* __restrict__ w2) {  // w2[HID2][HID1] -> g_W2T[HID1][HID2]
    int idx = blockIdx.x * blockDim.x + threadIdx.x;
    if (idx < HID2 * HID1) { int h = idx / HID1, j = idx - h * HID1; g_W2T[j * HID2 + h] = w2[idx]; }
}
__global__ void k_t3(const float* __restrict__ w3) {  // w3[OUTP][HID2] -> g_W3T[HID2][OUTP]
    int idx = blockIdx.x * blockDim.x + threadIdx.x;
    if (idx < OUTP * HID2) { int o = idx / HID2, j = idx - o * HID2; g_W3T[j * OUTP + o] = w3[idx]; }
}

// ---------------- fused SNN forward: 1 CTA (256 thr) per batch row ----------------
__global__ void __launch_bounds__(256)
k_snn(const float* __restrict__ obs,
      const float* __restrict__ enc_mean,
      const float* __restrict__ enc_std,
      const float* __restrict__ b1,
      const float* __restrict__ b2,
      const float* __restrict__ b3,
      const float* __restrict__ dec_w,
      const float* __restrict__ dec_b,
      float* __restrict__ out)
{
    const int b    = blockIdx.x;
    const int tid  = threadIdx.x;
    const int lane = tid & 31;
    const int wid  = tid >> 5;

    __shared__ unsigned short s_actJ[NIN];   // active input index (sorted, deterministic)
    __shared__ unsigned int   s_actM[NIN];   // its 25-bit spike-time mask
    __shared__ int            s_cnt[256];
    __shared__ unsigned int   s_m1[8];       // layer-1 spike bitmap (256 bits)
    __shared__ unsigned int   s_m2[8];       // layer-2 spike bitmap
    __shared__ float          s_pop[OUTP];

    // ================= population encoder (thread tid owns obs dim tid, 10 pop cells) ====
    const float o = obs[b * OBS_DIM + tid];
    unsigned int pm[POP_DIM];
    int myCount = 0;
#pragma unroll
    for (int p = 0; p < POP_DIM; ++p) {
        const int j  = tid * POP_DIM + p;
        const float m  = enc_mean[j];
        const float sd = enc_std[j];
        const float d  = o - m;
        const float a  = expf((-0.5f * (d * d)) / (sd * sd));
        float volt = 0.0f;
        unsigned int mask = 0u;
#pragma unroll
        for (int t = 0; t < T; ++t) {
            volt += a;
            if (volt > ENC_VTH) { mask |= (1u << t); volt -= ENC_VTH; }
        }
        pm[p] = mask;
        myCount += (mask != 0u);
    }

    // deterministic compaction: inclusive block scan of per-thread active counts
    s_cnt[tid] = myCount;
    __syncthreads();
    for (int off = 1; off < 256; off <<= 1) {
        int add = 0;
        if (tid >= off) add = s_cnt[tid - off];
        __syncthreads();
        s_cnt[tid] += add;
        __syncthreads();
    }
    int ofs = s_cnt[tid] - myCount;
    const int total = s_cnt[255];
#pragma unroll
    for (int p = 0; p < POP_DIM; ++p) {
        if (pm[p]) {
            s_actJ[ofs] = (unsigned short)(tid * POP_DIM + p);
            s_actM[ofs] = pm[p];
            ++ofs;
        }
    }
    __syncthreads();

    // ================= layer-1 "GEMM" over all 25 steps at once (sparse gather) =========
    float acc[T];
#pragma unroll
    for (int t = 0; t < T; ++t) acc[t] = 0.0f;

#pragma unroll 2
    for (int k = 0; k < total; ++k) {
        const int j          = (int)s_actJ[k];
        const unsigned int m = s_actM[k];
        const float w        = g_W1T[j * HID1 + tid];   // coalesced 1KB column, L2 hit
#pragma unroll
        for (int t = 0; t < T; ++t)
            if (m & (1u << t)) acc[t] += w;
    }

    // ================= temporal LIF stack =================================================
    const float b1v = b1[tid];
    const float b2v = b2[tid];
    const float b3v = (tid < OUTP) ? b3[tid] : 0.0f;

    float c1 = 0.f, v1 = 0.f, s1 = 0.f;
    float c2 = 0.f, v2 = 0.f, s2 = 0.f;
    float c3 = 0.f, v3 = 0.f, s3 = 0.f;
    float cnt3 = 0.f;

    for (int t = 0; t < T; ++t) {
        // ---- layer 1 (input = precomputed acc[t]) ----
        c1 = c1 * 0.5f + acc[t] + b1v;
        const float v1n  = v1 * 0.75f * (1.0f - s1) + c1;
        const float vth1 = 0.25f + 0.5f * (expf((v1 - v1n) / 3.0f) - 1.0f);
        v1 = v1n;
        s1 = (v1n > vth1) ? 1.0f : 0.0f;
        const unsigned bal1 = __ballot_sync(0xffffffffu, s1 != 0.0f);
        if (lane == 0) s_m1[wid] = bal1;
        __syncthreads();

        // ---- layer 2: gather active w2 columns ----
        float dot2 = 0.0f;
#pragma unroll
        for (int w8 = 0; w8 < 8; ++w8) {
            unsigned mw = s_m1[w8];                 // broadcast LDS; loop is warp-uniform
            while (mw) {
                const int bit = __ffs(mw) - 1;
                mw &= (mw - 1);
                dot2 += g_W2T[(w8 * 32 + bit) * HID2 + tid];
            }
        }
        c2 = c2 * 0.5f + dot2 + b2v;
        const float v2n  = v2 * 0.75f * (1.0f - s2) + c2;
        const float vth2 = 0.25f + 0.5f * (expf((v2 - v2n) / 3.0f) - 1.0f);
        v2 = v2n;
        s2 = (v2n > vth2) ? 1.0f : 0.0f;
        const unsigned bal2 = __ballot_sync(0xffffffffu, s2 != 0.0f);
        if (lane == 0) s_m2[wid] = bal2;
        __syncthreads();

        // ---- layer 3 (80 output neurons, threads 0..79) ----
        if (tid < OUTP) {
            float dot3 = 0.0f;
#pragma unroll
            for (int w8 = 0; w8 < 8; ++w8) {
                unsigned mw = s_m2[w8];
                while (mw) {
                    const int bit = __ffs(mw) - 1;
                    mw &= (mw - 1);
                    dot3 += g_W3T[(w8 * 32 + bit) * OUTP + tid];
                }
            }
            c3 = c3 * 0.5f + dot3 + b3v;
            const float v3n  = v3 * 0.75f * (1.0f - s3) + c3;
            const float vth3 = 0.25f + 0.5f * (expf((v3 - v3n) / 3.0f) - 1.0f);
            v3 = v3n;
            s3 = (v3n > vth3) ? 1.0f : 0.0f;
            cnt3 += s3;
        }
    }

    // ================= rate decode + grouped dot + tanh ===================================
    if (tid < OUTP) s_pop[tid] = cnt3 / 25.0f;
    __syncthreads();
    if (tid < ACT_DIM) {
        float raw = 0.0f;
#pragma unroll
        for (int p = 0; p < DE_POP; ++p)
            raw += s_pop[tid * DE_POP + p] * dec_w[tid * DE_POP + p];
        raw += dec_b[tid];
        out[b * ACT_DIM + tid] = tanhf(raw);
    }
}

// ---------------- launch ----------------
extern "C" void kernel_launch(void* const* d_in, const int* in_sizes, int n_in,
                              void* d_out, int out_size)
{
    const float* obs      = (const float*)d_in[0];
    const float* enc_mean = (const float*)d_in[1];
    const float* enc_std  = (const float*)d_in[2];
    const float* w1       = (const float*)d_in[3];
    const float* b1       = (const float*)d_in[4];
    const float* w2       = (const float*)d_in[5];
    const float* b2       = (const float*)d_in[6];
    const float* w3       = (const float*)d_in[7];
    const float* b3       = (const float*)d_in[8];
    const float* dec_w    = (const float*)d_in[9];
    const float* dec_b    = (const float*)d_in[10];

    const int B = in_sizes[0] / OBS_DIM;

    k_t1<<<(HID1 * NIN  + 255) / 256, 256>>>(w1);
    k_t2<<<(HID1 * HID2 + 255) / 256, 256>>>(w2);
    k_t3<<<(OUTP * HID2 + 255) / 256, 256>>>(w3);
    k_snn<<<B, 256>>>(obs, enc_mean, enc_std, b1, b2, b3, dec_w, dec_b, (float*)d_out);
}

// round 7
// speedup vs baseline: 5.3869x; 5.3869x over previous
#include <cuda_runtime.h>
#include <cstdint>

#define OBS_DIM 256
#define POP_DIM 10
#define NIN     (OBS_DIM * POP_DIM)   // 2560
#define HID1    256
#define HID2    256
#define OUTP    80                    // ACT_DIM * DE_POP
#define ACT_DIM 8
#define DE_POP  10
#define T       25
#define ENC_VTH 0.999f

// ---------------- scratch: transposed weights (column-contiguous gathers) ----------------
__device__ float g_W1T[NIN  * HID1];   // [j][h]  (2.62 MB, L2-resident)
__device__ float g_W2T[HID1 * HID2];   // [j][h]
__device__ float g_W3T[HID2 * OUTP];   // [j][o]

__global__ void k_t1(const float* __restrict__ w1) {
    int idx = blockIdx.x * blockDim.x + threadIdx.x;
    if (idx < HID1 * NIN) { int h = idx / NIN, j = idx - h * NIN; g_W1T[j * HID1 + h] = w1[idx]; }
}
__global__ void k_t2(const float* __restrict__ w2) {
    int idx = blockIdx.x * blockDim.x + threadIdx.x;
    if (idx < HID2 * HID1) { int h = idx / HID1, j = idx - h * HID1; g_W2T[j * HID2 + h] = w2[idx]; }
}
__global__ void k_t3(const float* __restrict__ w3) {
    int idx = blockIdx.x * blockDim.x + threadIdx.x;
    if (idx < OUTP * HID2) { int o = idx / HID2, j = idx - o * HID2; g_W3T[j * OUTP + o] = w3[idx]; }
}

// ---------------- helpers ----------------

// exclusive block scan over 256 threads (shfl warp scan + 8 warp totals).
// The leading __syncthreads also serves as the phase barrier protecting s_act reuse.
__device__ __forceinline__ int block_excl_scan(int val, int tid, int* s_warp, int* total_out)
{
    const int lane = tid & 31, wid = tid >> 5;
    int x = val;
#pragma unroll
    for (int o = 1; o < 32; o <<= 1) {
        int y = __shfl_up_sync(0xffffffffu, x, o);
        if (lane >= o) x += y;
    }
    __syncthreads();                     // all prior shared reads complete
    if (lane == 31) s_warp[wid] = x;
    __syncthreads();
    int woff = 0, tot = 0;
#pragma unroll
    for (int i = 0; i < 8; ++i) {
        int v = s_warp[i];
        tot += v;
        if (i < wid) woff += v;
    }
    *total_out = tot;
    return woff + (x - val);             // exclusive offset
}

// 25-step LIF with dynamic threshold; input acc[t], returns 25-bit spike mask.
__device__ __forceinline__ unsigned lif25(const float* acc, float bias)
{
    float c = 0.f, v = 0.f, s = 0.f;
    unsigned m = 0u;
#pragma unroll
    for (int t = 0; t < T; ++t) {
        c = c * 0.5f + acc[t] + bias;
        const float vn  = v * 0.75f * (1.0f - s) + c;
        const float vth = 0.25f + 0.5f * (expf((v - vn) * (1.0f / 3.0f)) - 1.0f);
        s = (vn > vth) ? 1.0f : 0.0f;
        v = vn;
        if (s != 0.0f) m |= (1u << t);
    }
    return m;
}

// Sparse "GEMM over all 25 steps": acc[t] += sum_{active j} W[j*stride+col] * bit(mask_j, t)
__device__ __forceinline__ void gather25(const float* __restrict__ W, int stride, int col,
                                         const uint2* __restrict__ list, int total,
                                         float acc[T])
{
#pragma unroll
    for (int t = 0; t < T; ++t) acc[t] = 0.0f;

    int k = 0;
    for (; k + 4 <= total; k += 4) {
        const uint2 e0 = list[k + 0];
        const uint2 e1 = list[k + 1];
        const uint2 e2 = list[k + 2];
        const uint2 e3 = list[k + 3];
        const float w0 = __ldg(W + (int)e0.x * stride + col);
        const float w1 = __ldg(W + (int)e1.x * stride + col);
        const float w2 = __ldg(W + (int)e2.x * stride + col);
        const float w3 = __ldg(W + (int)e3.x * stride + col);
#pragma unroll
        for (int t = 0; t < T; ++t) {
            float a = acc[t];
            if ((e0.y >> t) & 1u) a += w0;
            if ((e1.y >> t) & 1u) a += w1;
            if ((e2.y >> t) & 1u) a += w2;
            if ((e3.y >> t) & 1u) a += w3;
            acc[t] = a;
        }
    }
    for (; k < total; ++k) {
        const uint2 e = list[k];
        const float w = __ldg(W + (int)e.x * stride + col);
#pragma unroll
        for (int t = 0; t < T; ++t)
            if ((e.y >> t) & 1u) acc[t] += w;
    }
}

// ---------------- fused SNN forward: 1 CTA (256 thr) per batch row ----------------
__global__ void __launch_bounds__(256)
k_snn(const float* __restrict__ obs,
      const float* __restrict__ enc_mean,
      const float* __restrict__ enc_std,
      const float* __restrict__ b1,
      const float* __restrict__ b2,
      const float* __restrict__ b3,
      const float* __restrict__ dec_w,
      const float* __restrict__ dec_b,
      float* __restrict__ out)
{
    const int b   = blockIdx.x;
    const int tid = threadIdx.x;

    __shared__ uint2 s_act[NIN];   // (index, 25-bit spike mask) compacted active list
    __shared__ int   s_warp[8];
    __shared__ float s_pop[OUTP];

    // ===== population encoder: thread tid owns obs dim tid (10 pop cells) =====
    const float o = obs[b * OBS_DIM + tid];
    unsigned pm[POP_DIM];
    int myCount = 0;
#pragma unroll
    for (int p = 0; p < POP_DIM; ++p) {
        const int j    = tid * POP_DIM + p;
        const float m  = enc_mean[j];
        const float sd = enc_std[j];
        const float d  = o - m;
        const float a  = expf((-0.5f * (d * d)) / (sd * sd));
        float volt = 0.0f;
        unsigned mask = 0u;
#pragma unroll
        for (int t = 0; t < T; ++t) {
            volt += a;
            if (volt > ENC_VTH) { mask |= (1u << t); volt -= ENC_VTH; }
        }
        pm[p] = mask;
        myCount += (mask != 0u);
    }

    int total0;
    int ofs = block_excl_scan(myCount, tid, s_warp, &total0);
#pragma unroll
    for (int p = 0; p < POP_DIM; ++p) {
        if (pm[p]) { s_act[ofs] = make_uint2((unsigned)(tid * POP_DIM + p), pm[p]); ++ofs; }
    }
    __syncthreads();

    float acc[T];

    // ===== layer 1: gather over all 25 steps, then pure-register temporal LIF =====
    gather25(g_W1T, HID1, tid, s_act, total0, acc);
    const unsigned m1 = lif25(acc, b1[tid]);

    // compact layer-1 ever-active neurons (scan barrier protects s_act reuse)
    int tot1;
    int ofs1 = block_excl_scan(m1 != 0u ? 1 : 0, tid, s_warp, &tot1);
    if (m1) s_act[ofs1] = make_uint2((unsigned)tid, m1);
    __syncthreads();

    // ===== layer 2 =====
    gather25(g_W2T, HID2, tid, s_act, tot1, acc);
    const unsigned m2 = lif25(acc, b2[tid]);

    int tot2;
    int ofs2 = block_excl_scan(m2 != 0u ? 1 : 0, tid, s_warp, &tot2);
    if (m2) s_act[ofs2] = make_uint2((unsigned)tid, m2);
    __syncthreads();

    // ===== layer 3: 160 threads = 80 outputs x 2-way K split =====
    if (tid < 2 * OUTP) {
        const int oo = tid >> 1, half = tid & 1;
        float a3[T];
#pragma unroll
        for (int t = 0; t < T; ++t) a3[t] = 0.0f;

        for (int k = half; k < tot2; k += 2) {
            const uint2 e = s_act[k];
            const float w = __ldg(&g_W3T[(int)e.x * OUTP + oo]);
#pragma unroll
            for (int t = 0; t < T; ++t)
                if ((e.y >> t) & 1u) a3[t] += w;
        }
        // pair-reduce the two K halves (lanes 2o and 2o+1 are adjacent)
#pragma unroll
        for (int t = 0; t < T; ++t)
            a3[t] += __shfl_xor_sync(0xffffffffu, a3[t], 1);

        if (half == 0) {
            const float b3v = b3[oo];
            float c = 0.f, v = 0.f, s = 0.f, cnt = 0.f;
#pragma unroll
            for (int t = 0; t < T; ++t) {
                c = c * 0.5f + a3[t] + b3v;
                const float vn  = v * 0.75f * (1.0f - s) + c;
                const float vth = 0.25f + 0.5f * (expf((v - vn) * (1.0f / 3.0f)) - 1.0f);
                s = (vn > vth) ? 1.0f : 0.0f;
                v = vn;
                cnt += s;
            }
            s_pop[oo] = cnt * (1.0f / 25.0f);
        }
    }
    __syncthreads();

    // ===== decoder: grouped dot + tanh =====
    if (tid < ACT_DIM) {
        float raw = 0.0f;
#pragma unroll
        for (int p = 0; p < DE_POP; ++p)
            raw += s_pop[tid * DE_POP + p] * dec_w[tid * DE_POP + p];
        raw += dec_b[tid];
        out[b * ACT_DIM + tid] = tanhf(raw);
    }
}

// ---------------- launch ----------------
extern "C" void kernel_launch(void* const* d_in, const int* in_sizes, int n_in,
                              void* d_out, int out_size)
{
    const float* obs      = (const float*)d_in[0];
    const float* enc_mean = (const float*)d_in[1];
    const float* enc_std  = (const float*)d_in[2];
    const float* w1       = (const float*)d_in[3];
    const float* b1       = (const float*)d_in[4];
    const float* w2       = (const float*)d_in[5];
    const float* b2       = (const float*)d_in[6];
    const float* w3       = (const float*)d_in[7];
    const float* b3       = (const float*)d_in[8];
    const float* dec_w    = (const float*)d_in[9];
    const float* dec_b    = (const float*)d_in[10];

    const int B = in_sizes[0] / OBS_DIM;

    k_t1<<<(HID1 * NIN  + 255) / 256, 256>>>(w1);
    k_t2<<<(HID1 * HID2 + 255) / 256, 256>>>(w2);
    k_t3<<<(OUTP * HID2 + 255) / 256, 256>>>(w3);
    k_snn<<<B, 256>>>(obs, enc_mean, enc_std, b1, b2, b3, dec_w, dec_b, (float*)d_out);
}